// round 10
// baseline (speedup 1.0000x reference)
#include <cuda_runtime.h>
#include <cuda_bf16.h>
#include <math.h>
#include <stdint.h>

// x: (16, 256, 64, 64, 4) f32. Per (b,c) slab = 4096 float4 = 64 KB.
// Chunk = 2 batches = 32 MB. Serial chain:
//   L0: pool(c0); Lk: fused(scale c_{k-1}, pool c_k) k=1..7; L8: scale(c7).
// All kernels use 256-thread blocks at HALF-SLAB granularity (2 blocks/slab)
// for high occupancy. Pool maxes stored per half: g_pooled[bc][half].
// Stores are PLAIN (write-back) — stcs measured slower. Scale reads use ldcs.

#define NB 16
#define NC 256
#define SP 4096                      // float4 per (b,c)
#define HSP (SP / 2)                 // 2048 float4 per half slab
#define CHUNK_B 2
#define NCHUNKS (NB / CHUNK_B)       // 8
#define CHUNK_SLABS (CHUNK_B * NC)   // 512
#define TPB 256
#define HV (HSP / TPB)               // 8 float4 per thread per half slab

__device__ float4 g_pooled[NB * NC][2];   // per-half partial max

// ---------------------------------------------------------------------------
// Block max-reduce of m across 256 threads; thread 0 writes g_pooled[bc][half].
// ---------------------------------------------------------------------------
__device__ __forceinline__ void reduce_store_max(float4 m, int bc, int half,
                                                 float4* red) {
    const int t = threadIdx.x;
    #pragma unroll
    for (int o = 16; o > 0; o >>= 1) {
        m.x = fmaxf(m.x, __shfl_xor_sync(0xffffffffu, m.x, o));
        m.y = fmaxf(m.y, __shfl_xor_sync(0xffffffffu, m.y, o));
        m.z = fmaxf(m.z, __shfl_xor_sync(0xffffffffu, m.z, o));
        m.w = fmaxf(m.w, __shfl_xor_sync(0xffffffffu, m.w, o));
    }
    if ((t & 31) == 0) red[t >> 5] = m;
    __syncthreads();
    if (t == 0) {
        float4 r = red[0];
        #pragma unroll
        for (int w = 1; w < TPB / 32; w++) {
            r.x = fmaxf(r.x, red[w].x);
            r.y = fmaxf(r.y, red[w].y);
            r.z = fmaxf(r.z, red[w].z);
            r.w = fmaxf(r.w, red[w].w);
        }
        g_pooled[bc][half] = r;
    }
}

// ---------------------------------------------------------------------------
// Squeeze+excite for (b,c); 256 threads; result left in *u_sh (sync after).
// ---------------------------------------------------------------------------
__device__ __forceinline__ void compute_u(const float* __restrict__ comp_w,
                                          const float* __restrict__ comp_b,
                                          const float* __restrict__ exc_w,
                                          const float* __restrict__ exc_b,
                                          int b, int c,
                                          float4* red, float4* u_sh) {
    const int t = threadIdx.x;
    float4 pa = g_pooled[b * NC + t][0];
    float4 pb = g_pooled[b * NC + t][1];
    float4 p = make_float4(fmaxf(pa.x, pb.x), fmaxf(pa.y, pb.y),
                           fmaxf(pa.z, pb.z), fmaxf(pa.w, pb.w));
    float s0 = p.x * comp_w[0 * NC + t];
    float s1 = p.y * comp_w[1 * NC + t];
    float s2 = p.z * comp_w[2 * NC + t];
    float s3 = p.w * comp_w[3 * NC + t];
    #pragma unroll
    for (int o = 16; o > 0; o >>= 1) {
        s0 += __shfl_xor_sync(0xffffffffu, s0, o);
        s1 += __shfl_xor_sync(0xffffffffu, s1, o);
        s2 += __shfl_xor_sync(0xffffffffu, s2, o);
        s3 += __shfl_xor_sync(0xffffffffu, s3, o);
    }
    if ((t & 31) == 0) red[t >> 5] = make_float4(s0, s1, s2, s3);
    __syncthreads();
    if (t == 0) {
        float r  = comp_b[0];
        float xc = comp_b[1];
        float yc = comp_b[2];
        float zc = comp_b[3];
        #pragma unroll
        for (int w = 0; w < TPB / 32; w++) {
            r  += red[w].x;
            xc += red[w].y;
            yc += red[w].z;
            zc += red[w].w;
        }
        float u1r = r + xc + yc + zc;
        float u1x = xc - r - zc + yc;
        float u1y = yc + zc - r - xc;
        float u1z = zc - yc + xc - r;
        float r2 = u1r * exc_w[0 * NC + c] + exc_b[0 * NC + c];
        float x2 = u1x * exc_w[1 * NC + c] + exc_b[1 * NC + c];
        float y2 = u1y * exc_w[2 * NC + c] + exc_b[2 * NC + c];
        float z2 = u1z * exc_w[3 * NC + c] + exc_b[3 * NC + c];
        *u_sh = make_float4(r2 + x2 + y2 + z2,
                            x2 - r2 - z2 + y2,
                            y2 + z2 - r2 - x2,
                            z2 - y2 + x2 - r2);
    }
}

// ---------------------------------------------------------------------------
// Pool-only (prologue): one block per HALF slab, grid = 2*CHUNK_SLABS.
// ---------------------------------------------------------------------------
__global__ void __launch_bounds__(TPB) pool_kernel(const float* __restrict__ x,
                                                   int b0) {
    const int bc = b0 * NC + (int)(blockIdx.x >> 1);
    const int half = blockIdx.x & 1;
    const float4* xp = reinterpret_cast<const float4*>(x)
                       + (size_t)bc * SP + (size_t)half * HSP;
    const int t = threadIdx.x;

    float4 v[HV];
    #pragma unroll
    for (int j = 0; j < HV; j++) v[j] = xp[t + j * TPB];
    float4 m = v[0];
    #pragma unroll
    for (int j = 1; j < HV; j++) {
        m.x = fmaxf(m.x, v[j].x);
        m.y = fmaxf(m.y, v[j].y);
        m.z = fmaxf(m.z, v[j].z);
        m.w = fmaxf(m.w, v[j].w);
    }
    __shared__ float4 red[TPB / 32];
    reduce_store_max(m, bc, half, red);
}

// ---------------------------------------------------------------------------
// Fused: block handles HALF slab of pool chunk + same HALF slab of scale
// chunk, loads interleaved. Grid = 2*CHUNK_SLABS = 1024 blocks of 256 thr.
// ---------------------------------------------------------------------------
__global__ void __launch_bounds__(TPB) fused_kernel(const float* __restrict__ x,
                                                    const float* __restrict__ comp_w,
                                                    const float* __restrict__ comp_b,
                                                    const float* __restrict__ exc_w,
                                                    const float* __restrict__ exc_b,
                                                    float* __restrict__ out,
                                                    int scale_b0, int pool_b0) {
    const int slab = blockIdx.x >> 1;
    const int half = blockIdx.x & 1;
    const int sbc = scale_b0 * NC + slab;
    const int pbc = pool_b0 * NC + slab;
    const int t = threadIdx.x;

    __shared__ float4 red[TPB / 32];
    __shared__ float4 u_sh;

    compute_u(comp_w, comp_b, exc_w, exc_b, sbc >> 8, sbc & 255, red, &u_sh);
    __syncthreads();
    const float4 u = u_sh;

    const size_t hoff = (size_t)half * HSP;
    const float4* pp = reinterpret_cast<const float4*>(x) + (size_t)pbc * SP + hoff;
    const float4* sp = reinterpret_cast<const float4*>(x) + (size_t)sbc * SP + hoff;
    float4* op = reinterpret_cast<float4*>(out) + (size_t)sbc * SP + hoff;

    float4 m = make_float4(-INFINITY, -INFINITY, -INFINITY, -INFINITY);
    #pragma unroll
    for (int j0 = 0; j0 < HV; j0 += 4) {
        float4 pv[4], sv[4];
        #pragma unroll
        for (int j = 0; j < 4; j++) pv[j] = pp[t + (j0 + j) * TPB];
        #pragma unroll
        for (int j = 0; j < 4; j++) sv[j] = __ldcs(&sp[t + (j0 + j) * TPB]);
        #pragma unroll
        for (int j = 0; j < 4; j++) {
            m.x = fmaxf(m.x, pv[j].x);
            m.y = fmaxf(m.y, pv[j].y);
            m.z = fmaxf(m.z, pv[j].z);
            m.w = fmaxf(m.w, pv[j].w);
        }
        #pragma unroll
        for (int j = 0; j < 4; j++) {
            op[t + (j0 + j) * TPB] = make_float4(sv[j].x * u.x, sv[j].y * u.y,
                                                 sv[j].z * u.z, sv[j].w * u.w);
        }
    }
    __syncthreads();   // red[] reuse after compute_u
    reduce_store_max(m, pbc, half, red);
}

// ---------------------------------------------------------------------------
// Scale-only (epilogue): one block per HALF slab.
// ---------------------------------------------------------------------------
__global__ void __launch_bounds__(TPB) scale_kernel(const float* __restrict__ x,
                                                    const float* __restrict__ comp_w,
                                                    const float* __restrict__ comp_b,
                                                    const float* __restrict__ exc_w,
                                                    const float* __restrict__ exc_b,
                                                    float* __restrict__ out,
                                                    int b0) {
    const int bc = b0 * NC + (int)(blockIdx.x >> 1);
    const int half = blockIdx.x & 1;
    const int t = threadIdx.x;

    __shared__ float4 red[TPB / 32];
    __shared__ float4 u_sh;
    compute_u(comp_w, comp_b, exc_w, exc_b, bc >> 8, bc & 255, red, &u_sh);
    __syncthreads();
    const float4 u = u_sh;

    const size_t base = (size_t)bc * SP + (size_t)half * HSP;
    const float4* xp = reinterpret_cast<const float4*>(x) + base;
    float4* op = reinterpret_cast<float4*>(out) + base;
    #pragma unroll
    for (int j0 = 0; j0 < HV; j0 += 4) {
        float4 v[4];
        #pragma unroll
        for (int j = 0; j < 4; j++) v[j] = __ldcs(&xp[t + (j0 + j) * TPB]);
        #pragma unroll
        for (int j = 0; j < 4; j++) {
            op[t + (j0 + j) * TPB] = make_float4(v[j].x * u.x, v[j].y * u.y,
                                                 v[j].z * u.z, v[j].w * u.w);
        }
    }
}

extern "C" void kernel_launch(void* const* d_in, const int* in_sizes, int n_in,
                              void* d_out, int out_size) {
    const float* x      = (const float*)d_in[0];
    const float* comp_w = (const float*)d_in[1];
    const float* comp_b = (const float*)d_in[2];
    const float* exc_w  = (const float*)d_in[3];
    const float* exc_b  = (const float*)d_in[4];
    float* out = (float*)d_out;

    pool_kernel<<<2 * CHUNK_SLABS, TPB>>>(x, 0);
    for (int q = 0; q + 1 < NCHUNKS; q++) {
        fused_kernel<<<2 * CHUNK_SLABS, TPB>>>(x, comp_w, comp_b, exc_w, exc_b,
                                               out, q * CHUNK_B,
                                               (q + 1) * CHUNK_B);
    }
    scale_kernel<<<2 * CHUNK_SLABS, TPB>>>(x, comp_w, comp_b, exc_w, exc_b,
                                           out, (NCHUNKS - 1) * CHUNK_B);
}

// round 11
// speedup vs baseline: 1.2546x; 1.2546x over previous
#include <cuda_runtime.h>
#include <cuda_bf16.h>
#include <math.h>
#include <stdint.h>

// x: (16, 256, 64, 64, 4) f32. Per (b,c) slab = 4096 float4 = 64 KB.
// Chunk = 2 batches = 32 MB. Serial chain:
//   L0: pool(c0)
//   Lk: combined scale(c_{k-1}) + pool(c_k), k=1..7  (role-separated blocks)
//   L8: scale(c7)
// Combined grid = 1536: role = blockIdx.x%3. role 0 -> pool one full slab
// (64KB DRAM read); roles 1,2 -> scale one HALF slab (32KB L2 read + 32KB
// streamed write). Durations matched; roles spread across SMs.

#define NB 16
#define NC 256
#define SP 4096                      // float4 per (b,c)
#define HSP (SP / 2)
#define CHUNK_B 2
#define NCHUNKS (NB / CHUNK_B)       // 8
#define CHUNK_SLABS (CHUNK_B * NC)   // 512
#define TPB 256
#define GRP 8

__device__ float4 g_pooled[NB * NC];

// ---------------------------------------------------------------------------
__device__ __forceinline__ void do_pool(const float* __restrict__ x, int bc) {
    const float4* xp = reinterpret_cast<const float4*>(x) + (size_t)bc * SP;
    const int t = threadIdx.x;

    float4 m = make_float4(-INFINITY, -INFINITY, -INFINITY, -INFINITY);
    #pragma unroll
    for (int j0 = 0; j0 < SP / TPB; j0 += GRP) {
        float4 v[GRP];
        #pragma unroll
        for (int j = 0; j < GRP; j++) v[j] = xp[t + (j0 + j) * TPB];
        #pragma unroll
        for (int j = 0; j < GRP; j++) {
            m.x = fmaxf(m.x, v[j].x);
            m.y = fmaxf(m.y, v[j].y);
            m.z = fmaxf(m.z, v[j].z);
            m.w = fmaxf(m.w, v[j].w);
        }
    }
    #pragma unroll
    for (int o = 16; o > 0; o >>= 1) {
        m.x = fmaxf(m.x, __shfl_xor_sync(0xffffffffu, m.x, o));
        m.y = fmaxf(m.y, __shfl_xor_sync(0xffffffffu, m.y, o));
        m.z = fmaxf(m.z, __shfl_xor_sync(0xffffffffu, m.z, o));
        m.w = fmaxf(m.w, __shfl_xor_sync(0xffffffffu, m.w, o));
    }
    __shared__ float4 red[TPB / 32];
    const int lane = t & 31;
    const int warp = t >> 5;
    if (lane == 0) red[warp] = m;
    __syncthreads();
    if (t == 0) {
        float4 r = red[0];
        #pragma unroll
        for (int w = 1; w < TPB / 32; w++) {
            r.x = fmaxf(r.x, red[w].x);
            r.y = fmaxf(r.y, red[w].y);
            r.z = fmaxf(r.z, red[w].z);
            r.w = fmaxf(r.w, red[w].w);
        }
        g_pooled[bc] = r;
    }
}

// ---------------------------------------------------------------------------
// Scale one HALF slab of (b,c): redundant squeeze+excite, then out = x*u.
// ---------------------------------------------------------------------------
__device__ __forceinline__ void do_scale_half(const float* __restrict__ x,
                                              const float* __restrict__ comp_w,
                                              const float* __restrict__ comp_b,
                                              const float* __restrict__ exc_w,
                                              const float* __restrict__ exc_b,
                                              float* __restrict__ out,
                                              int bc, int half) {
    const int b = bc >> 8;
    const int c = bc & 255;
    const int t = threadIdx.x;
    const int lane = t & 31;
    const int warp = t >> 5;

    __shared__ float4 red[TPB / 32];
    __shared__ float4 u_sh;

    // Squeeze: thread t = channel t over pooled[b,:]
    float4 p = g_pooled[b * NC + t];
    float s0 = p.x * comp_w[0 * NC + t];
    float s1 = p.y * comp_w[1 * NC + t];
    float s2 = p.z * comp_w[2 * NC + t];
    float s3 = p.w * comp_w[3 * NC + t];
    #pragma unroll
    for (int o = 16; o > 0; o >>= 1) {
        s0 += __shfl_xor_sync(0xffffffffu, s0, o);
        s1 += __shfl_xor_sync(0xffffffffu, s1, o);
        s2 += __shfl_xor_sync(0xffffffffu, s2, o);
        s3 += __shfl_xor_sync(0xffffffffu, s3, o);
    }
    if (lane == 0) red[warp] = make_float4(s0, s1, s2, s3);
    __syncthreads();
    if (t == 0) {
        float r  = comp_b[0];
        float xc = comp_b[1];
        float yc = comp_b[2];
        float zc = comp_b[3];
        #pragma unroll
        for (int w = 0; w < TPB / 32; w++) {
            r  += red[w].x;
            xc += red[w].y;
            yc += red[w].z;
            zc += red[w].w;
        }
        float u1r = r + xc + yc + zc;
        float u1x = xc - r - zc + yc;
        float u1y = yc + zc - r - xc;
        float u1z = zc - yc + xc - r;
        float r2 = u1r * exc_w[0 * NC + c] + exc_b[0 * NC + c];
        float x2 = u1x * exc_w[1 * NC + c] + exc_b[1 * NC + c];
        float y2 = u1y * exc_w[2 * NC + c] + exc_b[2 * NC + c];
        float z2 = u1z * exc_w[3 * NC + c] + exc_b[3 * NC + c];
        u_sh = make_float4(r2 + x2 + y2 + z2,
                           x2 - r2 - z2 + y2,
                           y2 + z2 - r2 - x2,
                           z2 - y2 + x2 - r2);
    }
    __syncthreads();
    const float4 u = u_sh;

    const size_t base = (size_t)bc * SP + (size_t)half * HSP;
    const float4* xp = reinterpret_cast<const float4*>(x) + base;
    float4* op = reinterpret_cast<float4*>(out) + base;
    #pragma unroll
    for (int j0 = 0; j0 < HSP / TPB; j0 += GRP) {
        float4 v[GRP];
        #pragma unroll
        for (int j = 0; j < GRP; j++) v[j] = __ldcs(&xp[t + (j0 + j) * TPB]);
        #pragma unroll
        for (int j = 0; j < GRP; j++) {
            __stcs(&op[t + (j0 + j) * TPB],
                   make_float4(v[j].x * u.x, v[j].y * u.y,
                               v[j].z * u.z, v[j].w * u.w));
        }
    }
}

// ---------------------------------------------------------------------------
__global__ void __launch_bounds__(TPB) pool_only_kernel(const float* __restrict__ x,
                                                        int b0) {
    do_pool(x, b0 * NC + blockIdx.x);
}

__global__ void __launch_bounds__(TPB) scale_only_kernel(const float* __restrict__ x,
                                                         const float* __restrict__ comp_w,
                                                         const float* __restrict__ comp_b,
                                                         const float* __restrict__ exc_w,
                                                         const float* __restrict__ exc_b,
                                                         float* __restrict__ out,
                                                         int b0) {
    do_scale_half(x, comp_w, comp_b, exc_w, exc_b, out,
                  b0 * NC + (int)(blockIdx.x >> 1), blockIdx.x & 1);
}

__global__ void __launch_bounds__(TPB) combined_kernel(const float* __restrict__ x,
                                                       const float* __restrict__ comp_w,
                                                       const float* __restrict__ comp_b,
                                                       const float* __restrict__ exc_w,
                                                       const float* __restrict__ exc_b,
                                                       float* __restrict__ out,
                                                       int scale_b0, int pool_b0) {
    const int sid  = blockIdx.x / 3;
    const int role = blockIdx.x % 3;
    if (role == 0)
        do_pool(x, pool_b0 * NC + sid);
    else
        do_scale_half(x, comp_w, comp_b, exc_w, exc_b, out,
                      scale_b0 * NC + sid, role - 1);
}

extern "C" void kernel_launch(void* const* d_in, const int* in_sizes, int n_in,
                              void* d_out, int out_size) {
    const float* x      = (const float*)d_in[0];
    const float* comp_w = (const float*)d_in[1];
    const float* comp_b = (const float*)d_in[2];
    const float* exc_w  = (const float*)d_in[3];
    const float* exc_b  = (const float*)d_in[4];
    float* out = (float*)d_out;

    // Prologue: pool chunk 0 (512 blocks)
    pool_only_kernel<<<CHUNK_SLABS, TPB>>>(x, 0);
    // Steady state: scale(q) + pool(q+1), role-separated balanced blocks
    for (int q = 0; q + 1 < NCHUNKS; q++) {
        combined_kernel<<<3 * CHUNK_SLABS, TPB>>>(x, comp_w, comp_b,
                                                  exc_w, exc_b, out,
                                                  q * CHUNK_B,
                                                  (q + 1) * CHUNK_B);
    }
    // Epilogue: scale last chunk (1024 half-slab blocks)
    scale_only_kernel<<<2 * CHUNK_SLABS, TPB>>>(x, comp_w, comp_b,
                                                exc_w, exc_b, out,
                                                (NCHUNKS - 1) * CHUNK_B);
}